// round 14
// baseline (speedup 1.0000x reference)
#include <cuda_runtime.h>
#include <cuda_bf16.h>
#include <math.h>

#define B_   8192
#define F_   32
#define V_   64
#define C_   32
#define K_   8
#define KP_  7
#define FM1  31
#define EPS_ 1e-6f
#define VC_  (V_ * C_)          // 2048
#define VVC_ (V_ * V_ * C_)     // 131072
#define NFK  (FM1 * KP_)        // 217
#define HB_  (B_ / 2)           // 4096

#define NPREP   (32 + NFK * 8)  // 1768 prep-role blocks
#define NPAIR1  (HB_ / 4)       // 1024 fp32-pairs blocks (first half)
#define K1GRID  (2 * NPAIR1 + (NPREP - NPAIR1))   // 2792
#define K3GRID  (2 * 1024)      // 1024 bf16-full + 1024 mainT

// Scratch (no cudaMalloc allowed)
__device__ float g_T[F_ * VC_];               // fused gather table = 256KB
__device__ float g_sexp[NFK * 4 * VC_];       // pair exp-sum partials = 7.1MB
__device__ float g_psum[HB_ * C_];            // first-half pair partials = 512KB
__device__ __nv_bfloat16 g_ptb[NFK * VVC_];   // bf16 shadow = 56.9MB

// ---------------------------------------------------------------------------
// Compile-time (i,k) enumeration for gather n within feature range [i0,i1).
// ---------------------------------------------------------------------------
__host__ __device__ constexpr int IMIN_(int a, int b) { return a < b ? a : b; }
__host__ __device__ constexpr int gi_of(int n, int i0, int i1) {
    for (int i = i0; i < i1; i++) {
        int nk = IMIN_(i + 1, KP_);
        if (n < nk) return i;
        n -= nk;
    }
    return 0;
}
__host__ __device__ constexpr int gk_of(int n, int i0, int i1) {
    for (int i = i0; i < i1; i++) {
        int nk = IMIN_(i + 1, KP_);
        if (n < nk) return n;
        n -= nk;
    }
    return 0;
}

// fp32 paired gathers: one LDG.64 serves two gathers (16 lanes each).
template<int T, int NT, int I0, int I1, int BOFF>
struct PairLoop {
    static __device__ __forceinline__ void run(const int* __restrict__ xv,
                                               const float* __restrict__ s_w,
                                               const float* __restrict__ pt,
                                               int hw, int lc,
                                               float& a0, float& a1) {
        constexpr int iA = gi_of(2 * T,     I0, I1);
        constexpr int kA = gk_of(2 * T,     I0, I1);
        constexpr int iB = gi_of(2 * T + 1, I0, I1);
        constexpr int kB = gk_of(2 * T + 1, I0, I1);
        int offA = (iA * KP_ + kA) * VVC_ + xv[iA + 1 - BOFF] * VC_ + xv[iA - kA - BOFF] * C_;
        int offB = (iB * KP_ + kB) * VVC_ + xv[iB + 1 - BOFF] * VC_ + xv[iB - kB - BOFF] * C_;
        int off  = hw ? offB : offA;
        float w  = s_w[hw ? (iB * K_ + kB + 1) : (iA * K_ + kA + 1)];
        float2 v = __ldg((const float2*)(pt + off) + lc);
        a0 = fmaf(w, v.x, a0);
        a1 = fmaf(w, v.y, a1);
        PairLoop<T + 1, NT, I0, I1, BOFF>::run(xv, s_w, pt, hw, lc, a0, a1);
    }
};
template<int NT, int I0, int I1, int BOFF>
struct PairLoop<NT, NT, I0, I1, BOFF> {
    static __device__ __forceinline__ void run(const int*, const float*,
                                               const float*, int, int,
                                               float&, float&) {}
};

// bf16 paired gathers: one LDG.32 = 2 bf16 c-values; two gathers per instr.
template<int T, int NT, int I0, int I1, int BOFF>
struct PairLoopB {
    static __device__ __forceinline__ void run(const int* __restrict__ xv,
                                               const float* __restrict__ s_w,
                                               int hw, int lc,
                                               float& a0, float& a1) {
        constexpr int iA = gi_of(2 * T,     I0, I1);
        constexpr int kA = gk_of(2 * T,     I0, I1);
        constexpr int iB = gi_of(2 * T + 1, I0, I1);
        constexpr int kB = gk_of(2 * T + 1, I0, I1);
        int offA = (iA * KP_ + kA) * VVC_ + xv[iA + 1 - BOFF] * VC_ + xv[iA - kA - BOFF] * C_;
        int offB = (iB * KP_ + kB) * VVC_ + xv[iB + 1 - BOFF] * VC_ + xv[iB - kB - BOFF] * C_;
        int off  = hw ? offB : offA;
        float w  = s_w[hw ? (iB * K_ + kB + 1) : (iA * K_ + kA + 1)];
        unsigned int u = __ldg((const unsigned int*)(g_ptb + off) + lc);
        float vlo = __uint_as_float(u << 16);            // c = 2*lc
        float vhi = __uint_as_float(u & 0xffff0000u);    // c = 2*lc+1
        a0 = fmaf(w, vlo, a0);
        a1 = fmaf(w, vhi, a1);
        PairLoopB<T + 1, NT, I0, I1, BOFF>::run(xv, s_w, hw, lc, a0, a1);
    }
};
template<int NT, int I0, int I1, int BOFF>
struct PairLoopB<NT, NT, I0, I1, BOFF> {
    static __device__ __forceinline__ void run(const int*, const float*,
                                               int, int, float&, float&) {}
};

// ---------------------------------------------------------------------------
// Gate-row helper: gumbel-softmax weights for structure row i (0..30).
// ---------------------------------------------------------------------------
__device__ __forceinline__ void gate_row(int i, const float* __restrict__ sl,
                                         const float* __restrict__ un,
                                         float* __restrict__ wout) {
    int nv = 1 + ((i + 1 < KP_) ? (i + 1) : KP_);
    float gate[K_];
    float m = -1e30f;
#pragma unroll
    for (int k = 0; k < K_; k++) {
        if (k < nv) {
            float u = un[i * K_ + k];
            float g = -logf(-logf(u + EPS_) + EPS_);
            gate[k] = sl[i * K_ + k] + g;
            m = fmaxf(m, gate[k]);
        }
    }
    float s = 0.f;
#pragma unroll
    for (int k = 0; k < K_; k++)
        if (k < nv) { gate[k] = expf(gate[k] - m); s += gate[k]; }
    float inv = 1.f / s;
#pragma unroll
    for (int k = 0; k < K_; k++)
        wout[k] = (k < nv) ? gate[k] * inv : 0.f;
}

// ---------------------------------------------------------------------------
// Kernel 1: prep (build T, exp-sums, bf16 convert) interleaved with fp32
// pair gathers for the FIRST half of the batch (elements 0..4095).
//   bid < 2048 : even -> prep(bid/2), odd -> pairs(bid/2)
//   bid >= 2048: prep(1024 + bid - 2048)
// ---------------------------------------------------------------------------
__global__ void __launch_bounds__(256) k1(const int* __restrict__ x,
                                          const float* __restrict__ cls,
                                          const float* __restrict__ t0,
                                          const float* __restrict__ st,
                                          const float* __restrict__ pt,
                                          const float* __restrict__ sl,
                                          const float* __restrict__ un) {
    int bid = blockIdx.x;
    int tid = threadIdx.x;
    int role, ridx;
    if (bid < 2 * NPAIR1) { role = bid & 1; ridx = bid >> 1; }
    else                  { role = 0;       ridx = NPAIR1 + (bid - 2 * NPAIR1); }

    if (role == 1) {
        // ---- fp32 pairs role (first half of batch) ----
        __shared__ float  s_w[FM1 * K_];
        __shared__ float2 s_p2[8][16];
        if (tid < FM1) gate_row(tid, sl, un, &s_w[tid * K_]);
        __syncthreads();

        int warp = tid >> 5;
        int lane = tid & 31;
        int half = warp & 1;
        int hw   = lane >> 4;
        int lc   = lane & 15;
        int b    = ridx * 4 + (warp >> 1);      // 0..4095

        const int4* xr = (const int4*)(x + b * F_);
        float a0 = 0.f, a1 = 0.f;

        if (half == 0) {
            int xv[20];
#pragma unroll
            for (int q = 0; q < 5; q++) {
                int4 v = __ldg(&xr[q]);
                xv[4 * q + 0] = v.x; xv[4 * q + 1] = v.y;
                xv[4 * q + 2] = v.z; xv[4 * q + 3] = v.w;
            }
            PairLoop<0, 49, 0, 17, 0>::run(xv, s_w, pt, hw, lc, a0, a1);
        } else {
            int xv[24];
#pragma unroll
            for (int q = 2; q < 8; q++) {
                int4 v = __ldg(&xr[q]);
                xv[4 * q - 8] = v.x; xv[4 * q - 7] = v.y;
                xv[4 * q - 6] = v.z; xv[4 * q - 5] = v.w;
            }
            PairLoop<0, 49, 17, 31, 8>::run(xv, s_w, pt, hw, lc, a0, a1);
        }

        a0 += __shfl_down_sync(0xffffffffu, a0, 16);
        a1 += __shfl_down_sync(0xffffffffu, a1, 16);
        if (hw == 0) s_p2[warp][lc] = make_float2(a0, a1);
        __syncthreads();
        if (half == 0 && hw == 0) {
            float2 m = s_p2[warp][lc];
            float2 o = s_p2[warp + 1][lc];
            ((float2*)(g_psum + b * C_))[lc] = make_float2(m.x + o.x, m.y + o.y);
        }
        return;
    }

    // ---- prep role ----
    if (ridx >= 32) {
        int q    = ridx - 32;            // 0..1735
        int fk   = q >> 3;               // 0..216
        int part = q & 1;
        int vq   = (q >> 1) & 3;
        size_t slab = (size_t)fk * VVC_;
        int t = part * 256 + tid;
        const float4* base = (const float4*)(pt + slab) + vq * 16 * (VC_ / 4);
        uint2* outb = (uint2*)(g_ptb + slab) + vq * 16 * (VC_ / 4) + t;

        float s0 = 0.f, s1 = 0.f, s2 = 0.f, s3 = 0.f;
#pragma unroll
        for (int v = 0; v < 16; v++) {
            float4 r = __ldg(base + v * (VC_ / 4) + t);
            s0 += __expf(r.x); s1 += __expf(r.y);
            s2 += __expf(r.z); s3 += __expf(r.w);
            __nv_bfloat162 lo = __floats2bfloat162_rn(r.x, r.y);
            __nv_bfloat162 hi = __floats2bfloat162_rn(r.z, r.w);
            uint2 pk;
            pk.x = *(unsigned int*)&lo;
            pk.y = *(unsigned int*)&hi;
            outb[v * (VC_ / 4)] = pk;
        }
        float4 o; o.x = s0; o.y = s1; o.z = s2; o.w = s3;
        ((float4*)(g_sexp + (fk * 4 + vq) * VC_))[t] = o;
        return;
    }

    __shared__ float s_lse[C_];
    __shared__ float s_scalar;
    int j = ridx;

    if (j == 0) {
        if (tid == 0) {
            float m = -1e30f;
            for (int c = 0; c < C_; c++) m = fmaxf(m, cls[c]);
            float s = 0.f;
            for (int c = 0; c < C_; c++) s += expf(cls[c] - m);
            s_scalar = m + logf(s);
        }
        if (tid < C_) {
            float m = -1e30f;
            for (int v = 0; v < V_; v++) m = fmaxf(m, t0[v * C_ + tid]);
            float s = 0.f;
            for (int v = 0; v < V_; v++) s += expf(t0[v * C_ + tid] - m);
            s_lse[tid] = m + logf(s);
        }
        __syncthreads();
        for (int p = tid; p < VC_; p += blockDim.x) {
            int c = p & (C_ - 1);
            g_T[p] = (cls[c] - s_scalar) + (t0[p] - s_lse[c]);
        }
    } else {
        int f = j - 1;
        const float* stf = st + f * VC_;
        if (tid == 0) {
            float w[K_];
            gate_row(f, sl, un, w);
            s_scalar = w[0];
        }
        if (tid < C_) {
            float m = -1e30f;
            for (int v = 0; v < V_; v++) m = fmaxf(m, stf[v * C_ + tid]);
            float s = 0.f;
            for (int v = 0; v < V_; v++) s += expf(stf[v * C_ + tid] - m);
            s_lse[tid] = m + logf(s);
        }
        __syncthreads();
        float w0 = s_scalar;
        for (int p = tid; p < VC_; p += blockDim.x) {
            int c = p & (C_ - 1);
            g_T[j * VC_ + p] = w0 * (stf[p] - s_lse[c]);
        }
    }
}

// ---------------------------------------------------------------------------
// Kernel 2: fold weighted pair-LSE corrections into T (sum 4 partials + log).
// ---------------------------------------------------------------------------
__global__ void __launch_bounds__(1024) k_fold(const float* __restrict__ sl,
                                               const float* __restrict__ un) {
    __shared__ float s_w[FM1 * K_];
    if (threadIdx.x < FM1) gate_row(threadIdx.x, sl, un, &s_w[threadIdx.x * K_]);
    __syncthreads();

    int e = blockIdx.x * 1024 + threadIdx.x;
    int m = e >> 11;
    int p = e & (VC_ - 1);
    int jmax = (6 < 30 - m) ? 6 : (30 - m);
    float acc = 0.f;
#pragma unroll
    for (int jj = 0; jj < KP_; jj++) {
        if (jj <= jmax) {
            int i  = m + jj;
            int fk = i * KP_ + jj;
            float s = __ldg(&g_sexp[(fk * 4 + 0) * VC_ + p])
                    + __ldg(&g_sexp[(fk * 4 + 1) * VC_ + p])
                    + __ldg(&g_sexp[(fk * 4 + 2) * VC_ + p])
                    + __ldg(&g_sexp[(fk * 4 + 3) * VC_ + p]);
            acc = fmaf(s_w[i * K_ + jj + 1], __logf(s), acc);
        }
    }
    g_T[m * VC_ + p] -= acc;
}

// ---------------------------------------------------------------------------
// Kernel 3: second half via bf16 gathers + T + output (even bids) interleaved
// with mainT for the first half (odd bids).
// ---------------------------------------------------------------------------
__global__ void __launch_bounds__(256) k3(const int* __restrict__ x,
                                          const float* __restrict__ sl,
                                          const float* __restrict__ un,
                                          float* __restrict__ out) {
    int bid = blockIdx.x;
    int tid = threadIdx.x;
    int warp = tid >> 5;
    int lane = tid & 31;

    if (bid & 1) {
        // ---- mainT role: first half (elements 0..4095) ----
        __shared__ float s_part[8][C_];
        int ridx = bid >> 1;             // 0..1023
        int half = warp & 1;
        int b    = ridx * 4 + (warp >> 1);

        const int4* xr = (const int4*)(x + b * F_) + half * 4;
        int xv[16];
#pragma unroll
        for (int q = 0; q < 4; q++) {
            int4 v = __ldg(&xr[q]);
            xv[4 * q + 0] = v.x; xv[4 * q + 1] = v.y;
            xv[4 * q + 2] = v.z; xv[4 * q + 3] = v.w;
        }
        int jbase = half * 16;
        float a0 = 0.f, a1 = 0.f;
#pragma unroll
        for (int j = 0; j < 16; j++) {
            float t = __ldg(&g_T[((jbase + j) * V_ + xv[j]) * C_ + lane]);
            if (j & 1) a1 += t; else a0 += t;
        }
        float r = a0 + a1;
        s_part[warp][lane] = r;
        __syncthreads();
        if (half == 0)
            out[b * C_ + lane] = r + s_part[warp + 1][lane] + g_psum[b * C_ + lane];
        return;
    }

    // ---- full-element role: second half (elements 4096..8191), bf16 ----
    __shared__ float  s_w[FM1 * K_];
    __shared__ float  s_red[4][2][C_];   // pair partials, c-ordered
    __shared__ float  s_t1[4][C_];       // half1 T partials
    if (tid < FM1) gate_row(tid, sl, un, &s_w[tid * K_]);
    __syncthreads();

    int ridx = bid >> 1;                 // 0..1023
    int half = warp & 1;
    int hw   = lane >> 4;
    int lc   = lane & 15;
    int e    = warp >> 1;                // element-in-block 0..3
    int b    = HB_ + ridx * 4 + e;

    const int4* xr = (const int4*)(x + b * F_);
    float a0 = 0.f, a1 = 0.f;            // pair accums (c = 2lc, 2lc+1)
    float at = 0.f;                      // T accum (c = lane)

    if (half == 0) {
        int xv[20];
#pragma unroll
        for (int q = 0; q < 5; q++) {
            int4 v = __ldg(&xr[q]);
            xv[4 * q + 0] = v.x; xv[4 * q + 1] = v.y;
            xv[4 * q + 2] = v.z; xv[4 * q + 3] = v.w;
        }
        PairLoopB<0, 49, 0, 17, 0>::run(xv, s_w, hw, lc, a0, a1);
#pragma unroll
        for (int j = 0; j < 16; j++)
            at += __ldg(&g_T[(j * V_ + xv[j]) * C_ + lane]);
    } else {
        int xv[24];
#pragma unroll
        for (int q = 2; q < 8; q++) {
            int4 v = __ldg(&xr[q]);
            xv[4 * q - 8] = v.x; xv[4 * q - 7] = v.y;
            xv[4 * q - 6] = v.z; xv[4 * q - 5] = v.w;
        }
        PairLoopB<0, 49, 17, 31, 8>::run(xv, s_w, hw, lc, a0, a1);
#pragma unroll
        for (int j = 16; j < 32; j++)
            at += __ldg(&g_T[(j * V_ + xv[j - 8]) * C_ + lane]);
    }

    // Combine even/odd gather halves; stash partials.
    a0 += __shfl_down_sync(0xffffffffu, a0, 16);
    a1 += __shfl_down_sync(0xffffffffu, a1, 16);
    if (hw == 0) {
        s_red[e][half][2 * lc + 0] = a0;
        s_red[e][half][2 * lc + 1] = a1;
    }
    if (half == 1) s_t1[e][lane] = at;
    __syncthreads();
    if (half == 0) {
        out[b * C_ + lane] = at + s_t1[e][lane]
                           + s_red[e][0][lane] + s_red[e][1][lane];
    }
}

// ---------------------------------------------------------------------------
extern "C" void kernel_launch(void* const* d_in, const int* in_sizes, int n_in,
                              void* d_out, int out_size) {
    const int* x = (const int*)d_in[0];
    int idx = 1;
    if (in_sizes[1] == 1) idx = 2;   // skip scalar 'training' if present
    const float* cls = (const float*)d_in[idx++];
    const float* t0  = (const float*)d_in[idx++];
    const float* st  = (const float*)d_in[idx++];
    const float* pt  = (const float*)d_in[idx++];
    const float* sl  = (const float*)d_in[idx++];
    const float* un  = (const float*)d_in[idx++];
    float* out = (float*)d_out;

    k1<<<K1GRID, 256>>>(x, cls, t0, st, pt, sl, un);
    k_fold<<<62, 1024>>>(sl, un);
    k3<<<K3GRID, 256>>>(x, sl, un, out);
}

// round 15
// speedup vs baseline: 1.2822x; 1.2822x over previous
#include <cuda_runtime.h>
#include <math.h>

#define B_   8192
#define F_   32
#define V_   64
#define C_   32
#define K_   8
#define KP_  7
#define FM1  31
#define EPS_ 1e-6f
#define VC_  (V_ * C_)          // 2048
#define VVC_ (V_ * V_ * C_)     // 131072
#define NFK  (FM1 * KP_)        // 217

#define NPREP  (32 + NFK * 8)   // 1768 prep-role blocks
#define NPAIRS (B_ / 4)         // 2048 pairs-role blocks (4 elements each)
#define NINTER (2 * NPREP)      // 3536 interleaved region
#define NGRID  (NINTER + (NPAIRS - NPREP))   // 3816

// Scratch (no cudaMalloc allowed)
__device__ float g_T[F_ * VC_];             // fused gather table = 256KB
__device__ float g_sexp[NFK * 4 * VC_];     // pair exp-sum partials = 7.1MB
__device__ float g_psum[B_ * C_];           // per-element pair partial sums = 1MB

// ---------------------------------------------------------------------------
// Compile-time (i,k) enumeration for gather n within feature range [i0,i1).
// ---------------------------------------------------------------------------
__host__ __device__ constexpr int IMIN_(int a, int b) { return a < b ? a : b; }
__host__ __device__ constexpr int gi_of(int n, int i0, int i1) {
    for (int i = i0; i < i1; i++) {
        int nk = IMIN_(i + 1, KP_);
        if (n < nk) return i;
        n -= nk;
    }
    return 0;
}
__host__ __device__ constexpr int gk_of(int n, int i0, int i1) {
    for (int i = i0; i < i1; i++) {
        int nk = IMIN_(i + 1, KP_);
        if (n < nk) return n;
        n -= nk;
    }
    return 0;
}

// ---------------------------------------------------------------------------
// Batched pair-gather loop: each step issues STEP independent LDG.64 loads
// (one per pair of gathers; half-warp hw picks which gather of the pair),
// then does 2*STEP FMAs. Explicit batching maximizes loads in flight.
// ---------------------------------------------------------------------------
template<int T, int NT, int I0, int I1, int BOFF>
struct PairLoop4 {
    static constexpr int STEP = (NT - T >= 4) ? 4 : (NT - T);
    static __device__ __forceinline__ void run(const int* __restrict__ xv,
                                               const float* __restrict__ s_w,
                                               const float* __restrict__ pt,
                                               int hw, int lc,
                                               float& a0, float& a1) {
        float2 v[STEP];
        float  w[STEP];
#pragma unroll
        for (int s = 0; s < STEP; s++) {
            constexpr_lookup(s, xv, s_w, pt, hw, lc, v[s], w[s]);
        }
#pragma unroll
        for (int s = 0; s < STEP; s++) {
            a0 = fmaf(w[s], v[s].x, a0);
            a1 = fmaf(w[s], v[s].y, a1);
        }
        PairLoop4<T + STEP, NT, I0, I1, BOFF>::run(xv, s_w, pt, hw, lc, a0, a1);
    }
    template<int S> struct Idx {
        static constexpr int iA = gi_of(2 * (T + S),     I0, I1);
        static constexpr int kA = gk_of(2 * (T + S),     I0, I1);
        static constexpr int iB = gi_of(2 * (T + S) + 1, I0, I1);
        static constexpr int kB = gk_of(2 * (T + S) + 1, I0, I1);
    };
    static __device__ __forceinline__ void constexpr_lookup(
            int s, const int* __restrict__ xv, const float* __restrict__ s_w,
            const float* __restrict__ pt, int hw, int lc,
            float2& v, float& w) {
        // s is a compile-time constant at each unrolled call site; dispatch
        // through a switch that the compiler folds.
        switch (s) {
            case 0: load<0>(xv, s_w, pt, hw, lc, v, w); break;
            case 1: load<(STEP > 1) ? 1 : 0>(xv, s_w, pt, hw, lc, v, w); break;
            case 2: load<(STEP > 2) ? 2 : 0>(xv, s_w, pt, hw, lc, v, w); break;
            default: load<(STEP > 3) ? 3 : 0>(xv, s_w, pt, hw, lc, v, w); break;
        }
    }
    template<int S>
    static __device__ __forceinline__ void load(
            const int* __restrict__ xv, const float* __restrict__ s_w,
            const float* __restrict__ pt, int hw, int lc,
            float2& v, float& w) {
        constexpr int iA = Idx<S>::iA, kA = Idx<S>::kA;
        constexpr int iB = Idx<S>::iB, kB = Idx<S>::kB;
        int offA = (iA * KP_ + kA) * VVC_ + xv[iA + 1 - BOFF] * VC_ + xv[iA - kA - BOFF] * C_;
        int offB = (iB * KP_ + kB) * VVC_ + xv[iB + 1 - BOFF] * VC_ + xv[iB - kB - BOFF] * C_;
        int off  = hw ? offB : offA;
        w = s_w[hw ? (iB * K_ + kB + 1) : (iA * K_ + kA + 1)];
        v = __ldg((const float2*)(pt + off) + lc);
    }
};
template<int NT, int I0, int I1, int BOFF>
struct PairLoop4<NT, NT, I0, I1, BOFF> {
    static __device__ __forceinline__ void run(const int*, const float*,
                                               const float*, int, int,
                                               float&, float&) {}
};

// ---------------------------------------------------------------------------
// Gate-row helper: gumbel-softmax weights for structure row i (0..30).
// ---------------------------------------------------------------------------
__device__ __forceinline__ void gate_row(int i, const float* __restrict__ sl,
                                         const float* __restrict__ un,
                                         float* __restrict__ wout) {
    int nv = 1 + ((i + 1 < KP_) ? (i + 1) : KP_);
    float gate[K_];
    float m = -1e30f;
#pragma unroll
    for (int k = 0; k < K_; k++) {
        if (k < nv) {
            float u = un[i * K_ + k];
            float g = -logf(-logf(u + EPS_) + EPS_);
            gate[k] = sl[i * K_ + k] + g;
            m = fmaxf(m, gate[k]);
        }
    }
    float s = 0.f;
#pragma unroll
    for (int k = 0; k < K_; k++)
        if (k < nv) { gate[k] = expf(gate[k] - m); s += gate[k]; }
    float inv = 1.f / s;
#pragma unroll
    for (int k = 0; k < K_; k++)
        wout[k] = (k < nv) ? gate[k] * inv : 0.f;
}

// ---------------------------------------------------------------------------
// Fused kernel: interleaved roles (even bid -> prep, odd -> pairs in the
// first NINTER blocks). Pairs role: 4 elements/block, 2 warps/element,
// 49 paired LDG.64 gathers per warp issued in batches of 4.
// ---------------------------------------------------------------------------
__global__ void __launch_bounds__(256) k_fused(const int* __restrict__ x,
                                               const float* __restrict__ cls,
                                               const float* __restrict__ t0,
                                               const float* __restrict__ st,
                                               const float* __restrict__ pt,
                                               const float* __restrict__ sl,
                                               const float* __restrict__ un) {
    int bid = blockIdx.x;
    int tid = threadIdx.x;
    int role, ridx;
    if (bid < NINTER) { role = bid & 1; ridx = bid >> 1; }
    else              { role = 1;       ridx = NPREP + (bid - NINTER); }

    if (role == 1) {
        // =================== pairs role ===================
        __shared__ float  s_w[FM1 * K_];
        __shared__ float2 s_p2[8][16];
        if (tid < FM1) gate_row(tid, sl, un, &s_w[tid * K_]);
        __syncthreads();

        int warp = tid >> 5;
        int lane = tid & 31;
        int half = warp & 1;
        int hw   = lane >> 4;            // which gather of the pair
        int lc   = lane & 15;            // c-pair index (c = 2*lc, 2*lc+1)
        int b    = ridx * 4 + (warp >> 1);

        const int4* xr = (const int4*)(x + b * F_);
        float a0 = 0.f, a1 = 0.f;

        if (half == 0) {
            // i = 0..16 : 98 gathers = 49 pairs; needs x[0..17]
            int xv[20];
#pragma unroll
            for (int q = 0; q < 5; q++) {
                int4 v = __ldg(&xr[q]);
                xv[4 * q + 0] = v.x; xv[4 * q + 1] = v.y;
                xv[4 * q + 2] = v.z; xv[4 * q + 3] = v.w;
            }
            PairLoop4<0, 49, 0, 17, 0>::run(xv, s_w, pt, hw, lc, a0, a1);
        } else {
            // i = 17..30 : 98 gathers = 49 pairs; needs x[11..31], base 8
            int xv[24];
#pragma unroll
            for (int q = 2; q < 8; q++) {
                int4 v = __ldg(&xr[q]);
                xv[4 * q - 8] = v.x; xv[4 * q - 7] = v.y;
                xv[4 * q - 6] = v.z; xv[4 * q - 5] = v.w;
            }
            PairLoop4<0, 49, 17, 31, 8>::run(xv, s_w, pt, hw, lc, a0, a1);
        }

        // Combine even/odd gather halves within the warp.
        a0 += __shfl_down_sync(0xffffffffu, a0, 16);
        a1 += __shfl_down_sync(0xffffffffu, a1, 16);
        if (hw == 0) s_p2[warp][lc] = make_float2(a0, a1);
        __syncthreads();
        if (half == 0 && hw == 0) {
            float2 m = s_p2[warp][lc];
            float2 o = s_p2[warp + 1][lc];
            ((float2*)(g_psum + b * C_))[lc] = make_float2(m.x + o.x, m.y + o.y);
        }
        return;
    }

    // =================== prep role ===================
    if (ridx >= 32) {
        int q    = ridx - 32;            // 0..1735
        int fk   = q >> 3;               // 0..216
        int part = q & 1;
        int vq   = (q >> 1) & 3;
        const float4* base = (const float4*)(pt + (size_t)fk * VVC_)
                             + vq * 16 * (VC_ / 4);
        int t = part * 256 + tid;
        float s0 = 0.f, s1 = 0.f, s2 = 0.f, s3 = 0.f;
#pragma unroll
        for (int v = 0; v < 16; v++) {
            float4 r = __ldg(base + v * (VC_ / 4) + t);
            s0 += __expf(r.x); s1 += __expf(r.y);
            s2 += __expf(r.z); s3 += __expf(r.w);
        }
        float4 o; o.x = s0; o.y = s1; o.z = s2; o.w = s3;
        ((float4*)(g_sexp + (fk * 4 + vq) * VC_))[t] = o;
        return;
    }

    __shared__ float s_lse[C_];
    __shared__ float s_scalar;
    int j = ridx;

    if (j == 0) {
        if (tid == 0) {
            float m = -1e30f;
            for (int c = 0; c < C_; c++) m = fmaxf(m, cls[c]);
            float s = 0.f;
            for (int c = 0; c < C_; c++) s += expf(cls[c] - m);
            s_scalar = m + logf(s);
        }
        if (tid < C_) {
            float m = -1e30f;
            for (int v = 0; v < V_; v++) m = fmaxf(m, t0[v * C_ + tid]);
            float s = 0.f;
            for (int v = 0; v < V_; v++) s += expf(t0[v * C_ + tid] - m);
            s_lse[tid] = m + logf(s);
        }
        __syncthreads();
        for (int p = tid; p < VC_; p += blockDim.x) {
            int c = p & (C_ - 1);
            g_T[p] = (cls[c] - s_scalar) + (t0[p] - s_lse[c]);
        }
    } else {
        int f = j - 1;
        const float* stf = st + f * VC_;
        if (tid == 0) {
            float w[K_];
            gate_row(f, sl, un, w);
            s_scalar = w[0];
        }
        if (tid < C_) {
            float m = -1e30f;
            for (int v = 0; v < V_; v++) m = fmaxf(m, stf[v * C_ + tid]);
            float s = 0.f;
            for (int v = 0; v < V_; v++) s += expf(stf[v * C_ + tid] - m);
            s_lse[tid] = m + logf(s);
        }
        __syncthreads();
        float w0 = s_scalar;
        for (int p = tid; p < VC_; p += blockDim.x) {
            int c = p & (C_ - 1);
            g_T[j * VC_ + p] = w0 * (stf[p] - s_lse[c]);
        }
    }
}

// ---------------------------------------------------------------------------
// Kernel 2: fold weighted pair-LSE corrections into T (sum 4 partials + log).
// ---------------------------------------------------------------------------
__global__ void __launch_bounds__(1024) k_fold(const float* __restrict__ sl,
                                               const float* __restrict__ un) {
    __shared__ float s_w[FM1 * K_];
    if (threadIdx.x < FM1) gate_row(threadIdx.x, sl, un, &s_w[threadIdx.x * K_]);
    __syncthreads();

    int e = blockIdx.x * 1024 + threadIdx.x;
    int m = e >> 11;
    int p = e & (VC_ - 1);
    int jmax = (6 < 30 - m) ? 6 : (30 - m);
    float acc = 0.f;
#pragma unroll
    for (int jj = 0; jj < KP_; jj++) {
        if (jj <= jmax) {
            int i  = m + jj;
            int fk = i * KP_ + jj;
            float s = __ldg(&g_sexp[(fk * 4 + 0) * VC_ + p])
                    + __ldg(&g_sexp[(fk * 4 + 1) * VC_ + p])
                    + __ldg(&g_sexp[(fk * 4 + 2) * VC_ + p])
                    + __ldg(&g_sexp[(fk * 4 + 3) * VC_ + p]);
            acc = fmaf(s_w[i * K_ + jj + 1], __logf(s), acc);
        }
    }
    g_T[m * VC_ + p] -= acc;
}

// ---------------------------------------------------------------------------
// Kernel 3: T gathers + add pair partials. Two warps per element.
// ---------------------------------------------------------------------------
__global__ void __launch_bounds__(256) k_mainT(const int* __restrict__ x,
                                               float* __restrict__ out) {
    __shared__ float s_part[8][C_];
    int warp = threadIdx.x >> 5;
    int lane = threadIdx.x & 31;
    int half = warp & 1;
    int b    = blockIdx.x * 4 + (warp >> 1);

    const int4* xr = (const int4*)(x + b * F_) + half * 4;
    int xv[16];
#pragma unroll
    for (int q = 0; q < 4; q++) {
        int4 v = __ldg(&xr[q]);
        xv[4 * q + 0] = v.x; xv[4 * q + 1] = v.y;
        xv[4 * q + 2] = v.z; xv[4 * q + 3] = v.w;
    }
    int jbase = half * 16;
    float a0 = 0.f, a1 = 0.f;
#pragma unroll
    for (int j = 0; j < 16; j++) {
        float t = __ldg(&g_T[((jbase + j) * V_ + xv[j]) * C_ + lane]);
        if (j & 1) a1 += t; else a0 += t;
    }
    float r = a0 + a1;
    s_part[warp][lane] = r;
    __syncthreads();
    if (half == 0)
        out[b * C_ + lane] = r + s_part[warp + 1][lane] + g_psum[b * C_ + lane];
}

// ---------------------------------------------------------------------------
extern "C" void kernel_launch(void* const* d_in, const int* in_sizes, int n_in,
                              void* d_out, int out_size) {
    const int* x = (const int*)d_in[0];
    int idx = 1;
    if (in_sizes[1] == 1) idx = 2;   // skip scalar 'training' if present
    const float* cls = (const float*)d_in[idx++];
    const float* t0  = (const float*)d_in[idx++];
    const float* st  = (const float*)d_in[idx++];
    const float* pt  = (const float*)d_in[idx++];
    const float* sl  = (const float*)d_in[idx++];
    const float* un  = (const float*)d_in[idx++];
    float* out = (float*)d_out;

    k_fused<<<NGRID, 256>>>(x, cls, t0, st, pt, sl, un);
    k_fold<<<62, 1024>>>(sl, un);
    k_mainT<<<B_ / 4, 256>>>(x, out);
}